// round 15
// baseline (speedup 1.0000x reference)
#include <cuda_runtime.h>
#include <cuda_bf16.h>
#include <cuda_fp16.h>
#include <mma.h>
#include <math.h>
#include <stdint.h>

using namespace nvcuda;

#define B_ 2
#define T_ 2048
#define C_ 1024
#define H_ 16
#define D_ 64
#define M_ (B_*T_)
#define QSCALE 0.1803368801111437f  // (1/sqrt(64)) * log2(e)

typedef __half hf;

// ---------------------------------------------------------------------------
// Scratch (allocation-free contract: __device__ globals)
// ---------------------------------------------------------------------------
__device__ float2 g_cs[T_*32];
__device__ hf g_xh[M_*C_], g_xl[M_*C_];          // x split (fp16 2-term)
__device__ hf g_ah[M_*C_], g_al[M_*C_];          // attention out split
__device__ hf g_wh4[4][C_*C_];                    // weights single fp16
__device__ hf g_qh[B_*H_*T_*D_], g_ql[B_*H_*T_*D_];  // q split fp16
__device__ hf g_k[B_*H_*T_*D_];                   // k single fp16
__device__ hf g_v[B_*H_*T_*D_];                   // v single fp16

// ---------------------------------------------------------------------------
// cp.async / ldmatrix / mma helpers
// ---------------------------------------------------------------------------
#define CP_ASYNC16(dst, src) \
    asm volatile("cp.async.cg.shared.global [%0], [%1], 16;" :: "r"(dst), "l"(src) : "memory")
#define CP_COMMIT() asm volatile("cp.async.commit_group;" ::: "memory")
#define CP_WAIT0()  asm volatile("cp.async.wait_group 0;" ::: "memory")
#define CP_WAIT1()  asm volatile("cp.async.wait_group 1;" ::: "memory")

#define LDSM_X4(r0,r1,r2,r3, a) \
    asm volatile("ldmatrix.sync.aligned.m8n8.x4.shared.b16 {%0,%1,%2,%3}, [%4];" \
        : "=r"(r0),"=r"(r1),"=r"(r2),"=r"(r3) : "r"(a))
#define LDSM_X4T(r0,r1,r2,r3, a) \
    asm volatile("ldmatrix.sync.aligned.m8n8.x4.trans.shared.b16 {%0,%1,%2,%3}, [%4];" \
        : "=r"(r0),"=r"(r1),"=r"(r2),"=r"(r3) : "r"(a))

#define MMA_F16(d, a0,a1,a2,a3, b0,b1) \
    asm volatile("mma.sync.aligned.m16n8k16.row.col.f32.f16.f16.f32 " \
        "{%0,%1,%2,%3},{%4,%5,%6,%7},{%8,%9},{%0,%1,%2,%3};" \
        : "+f"((d)[0]),"+f"((d)[1]),"+f"((d)[2]),"+f"((d)[3]) \
        : "r"(a0),"r"(a1),"r"(a2),"r"(a3), "r"(b0),"r"(b1))

__device__ __forceinline__ uint32_t smem_u32(const void* p) {
    uint32_t a;
    asm("{ .reg .u64 t; cvta.to.shared.u64 t, %1; cvt.u32.u64 %0, t; }" : "=r"(a) : "l"(p));
    return a;
}

__device__ __forceinline__ uint32_t h2_u32(__half2 v) {
    return *reinterpret_cast<uint32_t*>(&v);
}

// ---------------------------------------------------------------------------
// FMA-pipe exp2: x <= 0
// ---------------------------------------------------------------------------
__device__ __forceinline__ float exp2p(float x)
{
    x = fmaxf(x, -125.0f);
    const float r = rintf(x);
    const float f = x - r;
    float p = 0.0013333558f;
    p = fmaf(p, f, 0.0096181291f);
    p = fmaf(p, f, 0.0555041087f);
    p = fmaf(p, f, 0.2402265070f);
    p = fmaf(p, f, 0.6931471806f);
    p = fmaf(p, f, 1.0f);
    const int e = (int)r;
    return p * __int_as_float((e + 127) << 23);
}

// ---------------------------------------------------------------------------
// RoPE table
// ---------------------------------------------------------------------------
__global__ void rope_table(float2* __restrict__ tab)
{
    const int idx = blockIdx.x * blockDim.x + threadIdx.x;
    if (idx >= T_*32) return;
    const int t = idx >> 5, i = idx & 31;
    const double inv = pow(10000.0, -(double)(2*i) / 64.0);
    const double ang = (double)t * inv;
    tab[idx] = make_float2((float)cos(ang), (float)sin(ang));
}

// ---------------------------------------------------------------------------
// fp32 -> (fp16 hi, fp16 lo) split for activations
// ---------------------------------------------------------------------------
__global__ __launch_bounds__(256)
void cvt_split_h(const float* __restrict__ in, hf* __restrict__ hi,
                 hf* __restrict__ lo, int n4)
{
    const int i = blockIdx.x * blockDim.x + threadIdx.x;
    if (i >= n4) return;
    const float4 v = ((const float4*)in)[i];
    const float f[4] = {v.x, v.y, v.z, v.w};
    hf h[4], l[4];
#pragma unroll
    for (int j = 0; j < 4; j++) {
        h[j] = __float2half_rn(f[j]);
        l[j] = __float2half_rn(f[j] - __half2float(h[j]));
    }
    ((__half2*)hi)[2*i]   = __half2(h[0], h[1]);
    ((__half2*)hi)[2*i+1] = __half2(h[2], h[3]);
    ((__half2*)lo)[2*i]   = __half2(l[0], l[1]);
    ((__half2*)lo)[2*i+1] = __half2(l[2], l[3]);
}

// all 4 weights -> single fp16, one launch
__global__ __launch_bounds__(256)
void cvt_w_h(const float* __restrict__ w0, const float* __restrict__ w1,
             const float* __restrict__ w2, const float* __restrict__ w3)
{
    const int i = blockIdx.x * blockDim.x + threadIdx.x;
    if (i >= C_*C_/4) return;
    const int z = blockIdx.z;
    const float* in = (z == 0) ? w0 : (z == 1) ? w1 : (z == 2) ? w2 : w3;
    const float4 v = ((const float4*)in)[i];
    hf* dst = g_wh4[z];
    ((__half2*)dst)[2*i]   = __floats2half2_rn(v.x, v.y);
    ((__half2*)dst)[2*i+1] = __floats2half2_rn(v.z, v.w);
}

// ---------------------------------------------------------------------------
// Pipelined wmma fp16 GEMM (cp.async double buffer), 2-term split:
// D = Ah*Wh + Al*Wh, fp32 accum.
// z=0: q (rope+qscale -> fp16 hi/lo scatter), z=1: k (rope -> single fp16),
// z=2: v (single fp16), z=3: fp32 out.
// ---------------------------------------------------------------------------
#define SLDB 40
#define TILE_HB (128*SLDB*2)
#define STAGE_HB (3*TILE_HB)
#define LDE 132
#define NCH2 (C_/32)

__device__ __forceinline__
void mma_gemm_body(const hf* __restrict__ Ah, const hf* __restrict__ Al,
                   const hf* __restrict__ Wh,
                   const float* __restrict__ bias,
                   hf* __restrict__ oh, hf* __restrict__ ol,
                   float* __restrict__ of,
                   const float2* __restrict__ cs, int z)
{
    extern __shared__ char smem[];
    const uint32_t sbase = smem_u32(smem);
    float* sEpi   = (float*)smem;
    float* bias_s = (float*)(smem + 67584);

    const int tid = threadIdx.x;
    const int wid = tid >> 5;
    const int wm = wid >> 2;
    const int wn = wid & 3;
    const int m0 = blockIdx.y << 7, n0 = blockIdx.x << 7;

    if (tid < 128) bias_s[tid] = bias[n0 + tid];

    const hf* srcs[3] = {Ah, Al, Wh};
    const int row0[3] = {m0, m0, n0};

    int jtile[6], jr[6], jv[6];
#pragma unroll
    for (int it = 0; it < 6; it++) {
        const int job = it * 256 + tid;
        jtile[it] = job >> 9;
        const int idx = job & 511;
        jr[it] = idx >> 2;
        jv[it] = idx & 3;
    }

#pragma unroll
    for (int it = 0; it < 6; it++) {
        const hf* g = srcs[jtile[it]] + (size_t)(row0[jtile[it]] + jr[it]) * C_ + jv[it]*8;
        CP_ASYNC16(sbase + jtile[it]*TILE_HB + jr[it]*80 + jv[it]*16, g);
    }
    CP_COMMIT();

    wmma::fragment<wmma::accumulator, 16, 16, 16, float> acc[4][2];
#pragma unroll
    for (int mt = 0; mt < 4; mt++)
#pragma unroll
        for (int nt = 0; nt < 2; nt++) wmma::fill_fragment(acc[mt][nt], 0.f);

    for (int kc = 0; kc < NCH2; kc++) {
        const int s = kc & 1;
        if (kc + 1 < NCH2) {
            const uint32_t db = sbase + (s^1)*STAGE_HB;
            const int koff = (kc+1)*32;
#pragma unroll
            for (int it = 0; it < 6; it++) {
                const hf* g = srcs[jtile[it]] + (size_t)(row0[jtile[it]] + jr[it]) * C_ + koff + jv[it]*8;
                CP_ASYNC16(db + jtile[it]*TILE_HB + jr[it]*80 + jv[it]*16, g);
            }
            CP_COMMIT();
            CP_WAIT1();
        } else {
            CP_WAIT0();
        }
        __syncthreads();

        hf* sT = (hf*)(smem + s*STAGE_HB);
#pragma unroll
        for (int ks = 0; ks < 2; ks++) {
            wmma::fragment<wmma::matrix_b, 16, 16, 16, hf, wmma::col_major> fwh[2];
#pragma unroll
            for (int nt = 0; nt < 2; nt++)
                wmma::load_matrix_sync(fwh[nt], sT + 2*(128*SLDB) + (wn*32 + nt*16)*SLDB + ks*16, SLDB);
#pragma unroll
            for (int mt = 0; mt < 4; mt++) {
                wmma::fragment<wmma::matrix_a, 16, 16, 16, hf, wmma::row_major> fah, fal;
                wmma::load_matrix_sync(fah, sT + 0*(128*SLDB) + (wm*64 + mt*16)*SLDB + ks*16, SLDB);
                wmma::load_matrix_sync(fal, sT + 1*(128*SLDB) + (wm*64 + mt*16)*SLDB + ks*16, SLDB);
#pragma unroll
                for (int nt = 0; nt < 2; nt++) {
                    wmma::mma_sync(acc[mt][nt], fah, fwh[nt], acc[mt][nt]);
                    wmma::mma_sync(acc[mt][nt], fal, fwh[nt], acc[mt][nt]);
                }
            }
        }
        __syncthreads();
    }

#pragma unroll
    for (int mt = 0; mt < 4; mt++)
#pragma unroll
        for (int nt = 0; nt < 2; nt++)
            wmma::store_matrix_sync(sEpi + (wm*64 + mt*16)*LDE + wn*32 + nt*16,
                                    acc[mt][nt], LDE, wmma::mem_row_major);
    __syncthreads();

    const int tx = tid & 15, ty = tid >> 4;
    const int n_base = n0 + 8*tx;
    const float4 b0 = *(const float4*)&bias_s[8*tx];
    const float4 b1 = *(const float4*)&bias_s[8*tx + 4];
    const float bb[8] = {b0.x, b0.y, b0.z, b0.w, b1.x, b1.y, b1.z, b1.w};

#pragma unroll
    for (int r = 0; r < 8; r++) {
        const int lrow = 8*ty + r;
        const int m = m0 + lrow;
        float o[8];
#pragma unroll
        for (int j = 0; j < 8; j++) o[j] = sEpi[lrow*LDE + 8*tx + j] + bb[j];

        if (z < 2) {  // RoPE
            const int t = m & (T_-1);
#pragma unroll
            for (int p = 0; p < 4; p++) {
                const int i = ((n_base + 2*p) & 63) >> 1;
                const float2 csv = cs[t*32 + i];
                const float x1 = o[2*p], x2 = o[2*p+1];
                o[2*p]   = x1*csv.x - x2*csv.y;
                o[2*p+1] = x1*csv.y + x2*csv.x;
            }
        }
        if (z == 0) {
#pragma unroll
            for (int j = 0; j < 8; j++) o[j] *= QSCALE;
        }

        if (z <= 2) {
            const int b = m >> 11, t = m & (T_-1);
            const int h = n_base >> 6, d = n_base & 63;
            const size_t doff = (((size_t)(b*H_ + h) * T_) + t) * D_ + d;
            hf h8[8];
#pragma unroll
            for (int j = 0; j < 8; j++) h8[j] = __float2half_rn(o[j]);
            *(uint4*)(oh + doff) = *(uint4*)h8;
            if (z == 0) {  // q also stores lo residual
                hf l8[8];
#pragma unroll
                for (int j = 0; j < 8; j++)
                    l8[j] = __float2half_rn(o[j] - __half2float(h8[j]));
                *(uint4*)(ol + doff) = *(uint4*)l8;
            }
        } else {
            float* dst = of + (size_t)m * C_ + n_base;
            *(float4*)dst = make_float4(o[0], o[1], o[2], o[3]);
            *(float4*)(dst + 4) = make_float4(o[4], o[5], o[6], o[7]);
        }
    }
}

__global__ __launch_bounds__(256, 2)
void qkv_mma(const hf* __restrict__ xh, const hf* __restrict__ xl,
             const float* __restrict__ bq, const float* __restrict__ bk,
             const float* __restrict__ bv, const float2* __restrict__ cs)
{
    const int z = blockIdx.z;
    const float* bias = (z == 0) ? bq : (z == 1) ? bk : bv;
    hf* oh = (z == 0) ? g_qh : (z == 1) ? g_k : g_v;
    hf* ol = (z == 0) ? g_ql : nullptr;
    mma_gemm_body(xh, xl, g_wh4[z], bias, oh, ol, nullptr, cs, z);
}

__global__ __launch_bounds__(256, 2)
void out_mma(const hf* __restrict__ ah, const hf* __restrict__ al,
             const float* __restrict__ bias, float* __restrict__ out)
{
    mma_gemm_body(ah, al, g_wh4[3], bias, nullptr, nullptr, out, nullptr, 3);
}

// ---------------------------------------------------------------------------
// Register-resident FA2 attention, fp16 2-term: Q=Qh+Ql, K single,
// P=Ph+Pl, V single. Triple-buffered cp.async K/V (2 tiles/stage).
// ---------------------------------------------------------------------------
#define ROWB 144
#define KVBUF 18432              // 2 tiles * 64 rows * 144B
#define ATTN_SMEM (3*KVBUF)      // 55296

__global__ __launch_bounds__(128, 2)
void attn_fa2(const hf* __restrict__ qh, const hf* __restrict__ ql,
              const hf* __restrict__ kk, const hf* __restrict__ vv,
              hf* __restrict__ ah_out, hf* __restrict__ al_out)
{
    extern __shared__ char smem[];
    const uint32_t sbase = smem_u32(smem);

    const int tid  = threadIdx.x;
    const int w    = tid >> 5;
    const int lane = tid & 31;
    const int tig  = lane & 3;
    const int grp  = lane >> 2;
    const int bh = blockIdx.y;
    const int b = bh >> 4, h = bh & (H_-1);
    const int qt = gridDim.x - 1 - blockIdx.x;
    const int q0 = qt << 6;

    const size_t hb = (size_t)bh * T_ * D_;
    const hf* qhb = qh + hb; const hf* qlb = ql + hb;
    const hf* kb_ = kk + hb; const hf* vb_ = vv + hb;

    // prefetch jobs: 1024 16B-vecs per stage, 8 per thread
    int jtile[8], jr[8], jv[8];
#pragma unroll
    for (int it = 0; it < 8; it++) {
        const int job = it * 128 + tid;
        jtile[it] = job >> 9;         // 0:k 1:v
        jr[it] = (job >> 3) & 63;
        jv[it] = job & 7;
    }
    const hf* ksrc[2] = {kb_, vb_};

#pragma unroll
    for (int it = 0; it < 8; it++)
        CP_ASYNC16(sbase + jtile[it]*9216 + jr[it]*ROWB + jv[it]*16,
                   ksrc[jtile[it]] + (size_t)jr[it]*D_ + jv[it]*8);
    CP_COMMIT();
    if (qt >= 1) {
#pragma unroll
        for (int it = 0; it < 8; it++)
            CP_ASYNC16(sbase + KVBUF + jtile[it]*9216 + jr[it]*ROWB + jv[it]*16,
                       ksrc[jtile[it]] + (size_t)(64*D_) + (size_t)jr[it]*D_ + jv[it]*8);
        CP_COMMIT();
    }

    // Q fragments (fp16 hi/lo) from gmem, kept for whole kernel
    uint32_t qfh[4][4], qfl[4][4];
    {
        const int r0 = q0 + w*16 + grp;
#pragma unroll
        for (int ks = 0; ks < 4; ks++) {
            const int c = ks*16 + tig*2;
            qfh[ks][0] = *(const uint32_t*)(qhb + (size_t)r0*D_ + c);
            qfh[ks][1] = *(const uint32_t*)(qhb + (size_t)(r0+8)*D_ + c);
            qfh[ks][2] = *(const uint32_t*)(qhb + (size_t)r0*D_ + c + 8);
            qfh[ks][3] = *(const uint32_t*)(qhb + (size_t)(r0+8)*D_ + c + 8);
            qfl[ks][0] = *(const uint32_t*)(qlb + (size_t)r0*D_ + c);
            qfl[ks][1] = *(const uint32_t*)(qlb + (size_t)(r0+8)*D_ + c);
            qfl[ks][2] = *(const uint32_t*)(qlb + (size_t)r0*D_ + c + 8);
            qfl[ks][3] = *(const uint32_t*)(qlb + (size_t)(r0+8)*D_ + c + 8);
        }
    }

    float o[8][4];
#pragma unroll
    for (int t = 0; t < 8; t++)
#pragma unroll
        for (int e = 0; e < 4; e++) o[t][e] = 0.f;

    float m0 = -1e30f, m1 = -1e30f, l0 = 0.f, l1 = 0.f;

    const uint32_t koffA = (uint32_t)((lane & 7) * ROWB + (lane >> 3) * 16);
    const uint32_t voffA = (uint32_t)(((lane >> 3) * 8 + (lane & 7)) * ROWB);

    for (int kt = 0; kt <= qt; kt++) {
        const uint32_t kb = sbase + (kt % 3)*KVBUF;
        const uint32_t vb = kb + 9216;

        if (kt < qt) { CP_WAIT1(); } else { CP_WAIT0(); }
        __syncthreads();

        if (kt + 2 <= qt) {
            const uint32_t db = sbase + ((kt+2) % 3)*KVBUF;
            const size_t soff = (size_t)(kt+2)*64*D_;
#pragma unroll
            for (int it = 0; it < 8; it++)
                CP_ASYNC16(db + jtile[it]*9216 + jr[it]*ROWB + jv[it]*16,
                           ksrc[jtile[it]] + soff + (size_t)jr[it]*D_ + jv[it]*8);
            CP_COMMIT();
        }

        // ---- QK^T (2-term) ----
        float s[8][4];
#pragma unroll
        for (int t = 0; t < 8; t++)
#pragma unroll
            for (int e = 0; e < 4; e++) s[t][e] = 0.f;

#pragma unroll
        for (int t = 0; t < 8; t++) {
#pragma unroll
            for (int kk2 = 0; kk2 < 2; kk2++) {
                uint32_t h0,h1,h2,h3;
                LDSM_X4(h0,h1,h2,h3, kb + (uint32_t)(t*8*ROWB) + (uint32_t)(kk2*64) + koffA);
                const int ks0 = 2*kk2, ks1 = 2*kk2 + 1;
                MMA_F16(s[t], qfh[ks0][0],qfh[ks0][1],qfh[ks0][2],qfh[ks0][3], h0,h1);
                MMA_F16(s[t], qfl[ks0][0],qfl[ks0][1],qfl[ks0][2],qfl[ks0][3], h0,h1);
                MMA_F16(s[t], qfh[ks1][0],qfh[ks1][1],qfh[ks1][2],qfh[ks1][3], h2,h3);
                MMA_F16(s[t], qfl[ks1][0],qfl[ks1][1],qfl[ks1][2],qfl[ks1][3], h2,h3);
            }
        }

        // ---- mask (diag tile only) ----
        if (kt == qt) {
            const int i0 = w*16 + grp, i1 = i0 + 8;
#pragma unroll
            for (int t = 0; t < 8; t++) {
                const int j = t*8 + tig*2;
                if (j   > i0) s[t][0] = -1e30f;
                if (j+1 > i0) s[t][1] = -1e30f;
                if (j   > i1) s[t][2] = -1e30f;
                if (j+1 > i1) s[t][3] = -1e30f;
            }
        }

        // ---- online softmax in registers ----
        float mx0 = -1e30f, mx1 = -1e30f;
#pragma unroll
        for (int t = 0; t < 8; t++) {
            mx0 = fmaxf(mx0, fmaxf(s[t][0], s[t][1]));
            mx1 = fmaxf(mx1, fmaxf(s[t][2], s[t][3]));
        }
        mx0 = fmaxf(mx0, __shfl_xor_sync(0xffffffffu, mx0, 1));
        mx0 = fmaxf(mx0, __shfl_xor_sync(0xffffffffu, mx0, 2));
        mx1 = fmaxf(mx1, __shfl_xor_sync(0xffffffffu, mx1, 1));
        mx1 = fmaxf(mx1, __shfl_xor_sync(0xffffffffu, mx1, 2));

        const float mn0 = fmaxf(m0, mx0), mn1 = fmaxf(m1, mx1);
        const float al0 = exp2p(m0 - mn0), al1 = exp2p(m1 - mn1);
        m0 = mn0; m1 = mn1;

        uint32_t pah0[8], pah1[8], pal0[8], pal1[8];
        float ps0 = 0.f, ps1 = 0.f;
#pragma unroll
        for (int t = 0; t < 8; t++) {
            const float p00 = exp2p(s[t][0] - mn0);
            const float p01 = exp2p(s[t][1] - mn0);
            const float p10 = exp2p(s[t][2] - mn1);
            const float p11 = exp2p(s[t][3] - mn1);
            ps0 += p00 + p01; ps1 += p10 + p11;
            const __half2 hp0 = __floats2half2_rn(p00, p01);
            const __half2 hp1 = __floats2half2_rn(p10, p11);
            pah0[t] = h2_u32(hp0);
            pah1[t] = h2_u32(hp1);
            const __half2 lp0 = __floats2half2_rn(p00 - __low2float(hp0),
                                                  p01 - __high2float(hp0));
            const __half2 lp1 = __floats2half2_rn(p10 - __low2float(hp1),
                                                  p11 - __high2float(hp1));
            pal0[t] = h2_u32(lp0);
            pal1[t] = h2_u32(lp1);
        }
        ps0 += __shfl_xor_sync(0xffffffffu, ps0, 1);
        ps0 += __shfl_xor_sync(0xffffffffu, ps0, 2);
        ps1 += __shfl_xor_sync(0xffffffffu, ps1, 1);
        ps1 += __shfl_xor_sync(0xffffffffu, ps1, 2);
        l0 = l0 * al0 + ps0;
        l1 = l1 * al1 + ps1;

#pragma unroll
        for (int t = 0; t < 8; t++) {
            o[t][0] *= al0; o[t][1] *= al0;
            o[t][2] *= al1; o[t][3] *= al1;
        }

        // ---- PV (2-term) ----
#pragma unroll
        for (int t = 0; t < 8; t++) {
#pragma unroll
            for (int kk2 = 0; kk2 < 2; kk2++) {
                uint32_t h0,h1,h2,h3;
                LDSM_X4T(h0,h1,h2,h3, vb + (uint32_t)(kk2*32*ROWB) + (uint32_t)(t*16) + voffA);
                const int ks0 = 2*kk2, ks1 = 2*kk2 + 1;
                MMA_F16(o[t], pah0[2*ks0],pah1[2*ks0],pah0[2*ks0+1],pah1[2*ks0+1], h0,h1);
                MMA_F16(o[t], pal0[2*ks0],pal1[2*ks0],pal0[2*ks0+1],pal1[2*ks0+1], h0,h1);
                MMA_F16(o[t], pah0[2*ks1],pah1[2*ks1],pah0[2*ks1+1],pah1[2*ks1+1], h2,h3);
                MMA_F16(o[t], pal0[2*ks1],pal1[2*ks1],pal0[2*ks1+1],pal1[2*ks1+1], h2,h3);
            }
        }
    }

    // ---- epilogue: normalize, fp16 split, store [M, C] ----
    const float il0 = 1.f / l0, il1 = 1.f / l1;
    const int r0g = q0 + w*16 + grp;
    const size_t base0 = ((size_t)(b*T_ + r0g)) * C_ + h*D_ + tig*2;
    const size_t base1 = ((size_t)(b*T_ + r0g + 8)) * C_ + h*D_ + tig*2;
#pragma unroll
    for (int t = 0; t < 8; t++) {
        const float v00 = o[t][0]*il0, v01 = o[t][1]*il0;
        const float v10 = o[t][2]*il1, v11 = o[t][3]*il1;
        const __half2 hp0 = __floats2half2_rn(v00, v01);
        const __half2 hp1 = __floats2half2_rn(v10, v11);
        const __half2 lp0 = __floats2half2_rn(v00 - __low2float(hp0), v01 - __high2float(hp0));
        const __half2 lp1 = __floats2half2_rn(v10 - __low2float(hp1), v11 - __high2float(hp1));
        *(__half2*)(ah_out + base0 + t*8) = hp0;
        *(__half2*)(ah_out + base1 + t*8) = hp1;
        *(__half2*)(al_out + base0 + t*8) = lp0;
        *(__half2*)(al_out + base1 + t*8) = lp1;
    }
}

// ---------------------------------------------------------------------------
extern "C" void kernel_launch(void* const* d_in, const int* in_sizes, int n_in,
                              void* d_out, int out_size)
{
    const float* x  = (const float*)d_in[0];
    const float* Wq = (const float*)d_in[1];
    const float* bq = (const float*)d_in[2];
    const float* Wk = (const float*)d_in[3];
    const float* bk = (const float*)d_in[4];
    const float* Wv = (const float*)d_in[5];
    const float* bv = (const float*)d_in[6];
    const float* Wo = (const float*)d_in[7];
    const float* bo = (const float*)d_in[8];
    float* out = (float*)d_out;

    float2* csp;
    hf *xh, *xl, *ah, *al;
    hf *qhp, *qlp, *kp, *vp;
    cudaGetSymbolAddress((void**)&csp,  g_cs);
    cudaGetSymbolAddress((void**)&xh,   g_xh);
    cudaGetSymbolAddress((void**)&xl,   g_xl);
    cudaGetSymbolAddress((void**)&ah,   g_ah);
    cudaGetSymbolAddress((void**)&al,   g_al);
    cudaGetSymbolAddress((void**)&qhp,  g_qh);
    cudaGetSymbolAddress((void**)&qlp,  g_ql);
    cudaGetSymbolAddress((void**)&kp,   g_k);
    cudaGetSymbolAddress((void**)&vp,   g_v);

    rope_table<<<(T_*32)/256, 256>>>(csp);

    cvt_split_h<<<(M_*C_/4)/256, 256>>>(x, xh, xl, M_*C_/4);
    cvt_w_h<<<dim3((C_*C_/4)/256, 1, 4), 256>>>(Wq, Wk, Wv, Wo);

    const size_t gsmem = 68096;
    cudaFuncSetAttribute(qkv_mma, cudaFuncAttributeMaxDynamicSharedMemorySize, (int)gsmem);
    cudaFuncSetAttribute(out_mma, cudaFuncAttributeMaxDynamicSharedMemorySize, (int)gsmem);
    cudaFuncSetAttribute(attn_fa2, cudaFuncAttributeMaxDynamicSharedMemorySize, ATTN_SMEM);

    qkv_mma<<<dim3(C_/128, M_/128, 3), 256, gsmem>>>(xh, xl, bq, bk, bv, csp);

    attn_fa2<<<dim3(T_/64, B_*H_), 128, ATTN_SMEM>>>(qhp, qlp, kp, vp, ah, al);

    out_mma<<<dim3(C_/128, M_/128), 256, gsmem>>>(ah, al, bo, out);
}

// round 16
// speedup vs baseline: 1.6002x; 1.6002x over previous
#include <cuda_runtime.h>
#include <cuda_bf16.h>
#include <cuda_fp16.h>
#include <mma.h>
#include <math.h>
#include <stdint.h>

using namespace nvcuda;

#define B_ 2
#define T_ 2048
#define C_ 1024
#define H_ 16
#define D_ 64
#define M_ (B_*T_)
#define QSCALE 0.1803368801111437f  // (1/sqrt(64)) * log2(e)

typedef __half hf;

// ---------------------------------------------------------------------------
// Scratch (allocation-free contract: __device__ globals)
// ---------------------------------------------------------------------------
__device__ float2 g_cs[T_*32];
__device__ hf g_xh[M_*C_], g_xl[M_*C_];          // x split (fp16 2-term)
__device__ hf g_ah[M_*C_], g_al[M_*C_];          // attention out split
__device__ hf g_wh4[4][C_*C_];                    // weights single fp16
__device__ hf g_qh[B_*H_*T_*D_], g_ql[B_*H_*T_*D_];  // q split fp16
__device__ hf g_k[B_*H_*T_*D_];                   // k single fp16
__device__ hf g_v[B_*H_*T_*D_];                   // v single fp16

// ---------------------------------------------------------------------------
// cp.async / ldmatrix / mma helpers
// ---------------------------------------------------------------------------
#define CP_ASYNC16(dst, src) \
    asm volatile("cp.async.cg.shared.global [%0], [%1], 16;" :: "r"(dst), "l"(src) : "memory")
#define CP_COMMIT() asm volatile("cp.async.commit_group;" ::: "memory")
#define CP_WAIT0()  asm volatile("cp.async.wait_group 0;" ::: "memory")
#define CP_WAIT1()  asm volatile("cp.async.wait_group 1;" ::: "memory")

#define LDSM_X4(r0,r1,r2,r3, a) \
    asm volatile("ldmatrix.sync.aligned.m8n8.x4.shared.b16 {%0,%1,%2,%3}, [%4];" \
        : "=r"(r0),"=r"(r1),"=r"(r2),"=r"(r3) : "r"(a))
#define LDSM_X4T(r0,r1,r2,r3, a) \
    asm volatile("ldmatrix.sync.aligned.m8n8.x4.trans.shared.b16 {%0,%1,%2,%3}, [%4];" \
        : "=r"(r0),"=r"(r1),"=r"(r2),"=r"(r3) : "r"(a))

#define MMA_F16(d, a0,a1,a2,a3, b0,b1) \
    asm volatile("mma.sync.aligned.m16n8k16.row.col.f32.f16.f16.f32 " \
        "{%0,%1,%2,%3},{%4,%5,%6,%7},{%8,%9},{%0,%1,%2,%3};" \
        : "+f"((d)[0]),"+f"((d)[1]),"+f"((d)[2]),"+f"((d)[3]) \
        : "r"(a0),"r"(a1),"r"(a2),"r"(a3), "r"(b0),"r"(b1))

__device__ __forceinline__ uint32_t smem_u32(const void* p) {
    uint32_t a;
    asm("{ .reg .u64 t; cvta.to.shared.u64 t, %1; cvt.u32.u64 %0, t; }" : "=r"(a) : "l"(p));
    return a;
}

__device__ __forceinline__ uint32_t h2_u32(__half2 v) {
    return *reinterpret_cast<uint32_t*>(&v);
}

// ---------------------------------------------------------------------------
// FMA-pipe exp2: x <= 0
// ---------------------------------------------------------------------------
__device__ __forceinline__ float exp2p(float x)
{
    x = fmaxf(x, -125.0f);
    const float r = rintf(x);
    const float f = x - r;
    float p = 0.0013333558f;
    p = fmaf(p, f, 0.0096181291f);
    p = fmaf(p, f, 0.0555041087f);
    p = fmaf(p, f, 0.2402265070f);
    p = fmaf(p, f, 0.6931471806f);
    p = fmaf(p, f, 1.0f);
    const int e = (int)r;
    return p * __int_as_float((e + 127) << 23);
}

// ---------------------------------------------------------------------------
// RoPE table
// ---------------------------------------------------------------------------
__global__ void rope_table(float2* __restrict__ tab)
{
    const int idx = blockIdx.x * blockDim.x + threadIdx.x;
    if (idx >= T_*32) return;
    const int t = idx >> 5, i = idx & 31;
    const double inv = pow(10000.0, -(double)(2*i) / 64.0);
    const double ang = (double)t * inv;
    tab[idx] = make_float2((float)cos(ang), (float)sin(ang));
}

// ---------------------------------------------------------------------------
// fp32 -> (fp16 hi, fp16 lo) split for activations
// ---------------------------------------------------------------------------
__global__ __launch_bounds__(256)
void cvt_split_h(const float* __restrict__ in, hf* __restrict__ hi,
                 hf* __restrict__ lo, int n4)
{
    const int i = blockIdx.x * blockDim.x + threadIdx.x;
    if (i >= n4) return;
    const float4 v = ((const float4*)in)[i];
    const float f[4] = {v.x, v.y, v.z, v.w};
    hf h[4], l[4];
#pragma unroll
    for (int j = 0; j < 4; j++) {
        h[j] = __float2half_rn(f[j]);
        l[j] = __float2half_rn(f[j] - __half2float(h[j]));
    }
    ((__half2*)hi)[2*i]   = __half2(h[0], h[1]);
    ((__half2*)hi)[2*i+1] = __half2(h[2], h[3]);
    ((__half2*)lo)[2*i]   = __half2(l[0], l[1]);
    ((__half2*)lo)[2*i+1] = __half2(l[2], l[3]);
}

// all 4 weights -> single fp16, one launch
__global__ __launch_bounds__(256)
void cvt_w_h(const float* __restrict__ w0, const float* __restrict__ w1,
             const float* __restrict__ w2, const float* __restrict__ w3)
{
    const int i = blockIdx.x * blockDim.x + threadIdx.x;
    if (i >= C_*C_/4) return;
    const int z = blockIdx.z;
    const float* in = (z == 0) ? w0 : (z == 1) ? w1 : (z == 2) ? w2 : w3;
    const float4 v = ((const float4*)in)[i];
    hf* dst = g_wh4[z];
    ((__half2*)dst)[2*i]   = __floats2half2_rn(v.x, v.y);
    ((__half2*)dst)[2*i+1] = __floats2half2_rn(v.z, v.w);
}

// ---------------------------------------------------------------------------
// Pipelined wmma fp16 GEMM, 2-term split, KC=64 chunks (16 iterations),
// cp.async double buffer. D = Ah*Wh + Al*Wh, fp32 accum.
// z=0: q (rope+qscale -> fp16 hi/lo scatter), z=1: k (rope -> single fp16),
// z=2: v (single fp16), z=3: fp32 out.
// ---------------------------------------------------------------------------
#define SLDB 72                        // fp16 leading dim (144B rows)
#define TILE_HB (128*SLDB*2)           // 18432 B per tile
#define STAGE_HB (3*TILE_HB)           // 55296 B per stage
#define LDE 132
#define NCH (C_/64)                    // 16 chunks

__device__ __forceinline__
void mma_gemm_body(const hf* __restrict__ Ah, const hf* __restrict__ Al,
                   const hf* __restrict__ Wh,
                   const float* __restrict__ bias,
                   hf* __restrict__ oh, hf* __restrict__ ol,
                   float* __restrict__ of,
                   const float2* __restrict__ cs, int z)
{
    extern __shared__ char smem[];
    const uint32_t sbase = smem_u32(smem);
    float* sEpi   = (float*)smem;                  // 67584 B (aliases stages)
    float* bias_s = (float*)(smem + 2*STAGE_HB);   // at 110592

    const int tid = threadIdx.x;
    const int wid = tid >> 5;
    const int wm = wid >> 2;
    const int wn = wid & 3;
    const int m0 = blockIdx.y << 7, n0 = blockIdx.x << 7;

    if (tid < 128) bias_s[tid] = bias[n0 + tid];

    const hf* srcs[3] = {Ah, Al, Wh};
    const int row0[3] = {m0, m0, n0};

    // 3072 16B-vec jobs per chunk, 12 per thread
    int jtile[12], jr[12], jv[12];
#pragma unroll
    for (int it = 0; it < 12; it++) {
        const int job = it * 256 + tid;
        jtile[it] = job >> 10;
        const int idx = job & 1023;
        jr[it] = idx >> 3;
        jv[it] = idx & 7;
    }

#pragma unroll
    for (int it = 0; it < 12; it++) {
        const hf* g = srcs[jtile[it]] + (size_t)(row0[jtile[it]] + jr[it]) * C_ + jv[it]*8;
        CP_ASYNC16(sbase + jtile[it]*TILE_HB + jr[it]*144 + jv[it]*16, g);
    }
    CP_COMMIT();

    wmma::fragment<wmma::accumulator, 16, 16, 16, float> acc[4][2];
#pragma unroll
    for (int mt = 0; mt < 4; mt++)
#pragma unroll
        for (int nt = 0; nt < 2; nt++) wmma::fill_fragment(acc[mt][nt], 0.f);

    for (int kc = 0; kc < NCH; kc++) {
        const int s = kc & 1;
        if (kc + 1 < NCH) {
            const uint32_t db = sbase + (s^1)*STAGE_HB;
            const int koff = (kc+1)*64;
#pragma unroll
            for (int it = 0; it < 12; it++) {
                const hf* g = srcs[jtile[it]] + (size_t)(row0[jtile[it]] + jr[it]) * C_ + koff + jv[it]*8;
                CP_ASYNC16(db + jtile[it]*TILE_HB + jr[it]*144 + jv[it]*16, g);
            }
            CP_COMMIT();
            CP_WAIT1();
        } else {
            CP_WAIT0();
        }
        __syncthreads();

        hf* sT = (hf*)(smem + s*STAGE_HB);
#pragma unroll
        for (int ks = 0; ks < 4; ks++) {
            wmma::fragment<wmma::matrix_b, 16, 16, 16, hf, wmma::col_major> fwh[2];
#pragma unroll
            for (int nt = 0; nt < 2; nt++)
                wmma::load_matrix_sync(fwh[nt], sT + 2*(128*SLDB) + (wn*32 + nt*16)*SLDB + ks*16, SLDB);
#pragma unroll
            for (int mt = 0; mt < 4; mt++) {
                wmma::fragment<wmma::matrix_a, 16, 16, 16, hf, wmma::row_major> fah, fal;
                wmma::load_matrix_sync(fah, sT + 0*(128*SLDB) + (wm*64 + mt*16)*SLDB + ks*16, SLDB);
                wmma::load_matrix_sync(fal, sT + 1*(128*SLDB) + (wm*64 + mt*16)*SLDB + ks*16, SLDB);
#pragma unroll
                for (int nt = 0; nt < 2; nt++) {
                    wmma::mma_sync(acc[mt][nt], fah, fwh[nt], acc[mt][nt]);
                    wmma::mma_sync(acc[mt][nt], fal, fwh[nt], acc[mt][nt]);
                }
            }
        }
        __syncthreads();
    }

#pragma unroll
    for (int mt = 0; mt < 4; mt++)
#pragma unroll
        for (int nt = 0; nt < 2; nt++)
            wmma::store_matrix_sync(sEpi + (wm*64 + mt*16)*LDE + wn*32 + nt*16,
                                    acc[mt][nt], LDE, wmma::mem_row_major);
    __syncthreads();

    const int tx = tid & 15, ty = tid >> 4;
    const int n_base = n0 + 8*tx;
    const float4 b0 = *(const float4*)&bias_s[8*tx];
    const float4 b1 = *(const float4*)&bias_s[8*tx + 4];
    const float bb[8] = {b0.x, b0.y, b0.z, b0.w, b1.x, b1.y, b1.z, b1.w};

#pragma unroll
    for (int r = 0; r < 8; r++) {
        const int lrow = 8*ty + r;
        const int m = m0 + lrow;
        float o[8];
#pragma unroll
        for (int j = 0; j < 8; j++) o[j] = sEpi[lrow*LDE + 8*tx + j] + bb[j];

        if (z < 2) {  // RoPE
            const int t = m & (T_-1);
#pragma unroll
            for (int p = 0; p < 4; p++) {
                const int i = ((n_base + 2*p) & 63) >> 1;
                const float2 csv = cs[t*32 + i];
                const float x1 = o[2*p], x2 = o[2*p+1];
                o[2*p]   = x1*csv.x - x2*csv.y;
                o[2*p+1] = x1*csv.y + x2*csv.x;
            }
        }
        if (z == 0) {
#pragma unroll
            for (int j = 0; j < 8; j++) o[j] *= QSCALE;
        }

        if (z <= 2) {
            const int b = m >> 11, t = m & (T_-1);
            const int h = n_base >> 6, d = n_base & 63;
            const size_t doff = (((size_t)(b*H_ + h) * T_) + t) * D_ + d;
            hf h8[8];
#pragma unroll
            for (int j = 0; j < 8; j++) h8[j] = __float2half_rn(o[j]);
            *(uint4*)(oh + doff) = *(uint4*)h8;
            if (z == 0) {
                hf l8[8];
#pragma unroll
                for (int j = 0; j < 8; j++)
                    l8[j] = __float2half_rn(o[j] - __half2float(h8[j]));
                *(uint4*)(ol + doff) = *(uint4*)l8;
            }
        } else {
            float* dst = of + (size_t)m * C_ + n_base;
            *(float4*)dst = make_float4(o[0], o[1], o[2], o[3]);
            *(float4*)(dst + 4) = make_float4(o[4], o[5], o[6], o[7]);
        }
    }
}

__global__ __launch_bounds__(256, 2)
void qkv_mma(const hf* __restrict__ xh, const hf* __restrict__ xl,
             const float* __restrict__ bq, const float* __restrict__ bk,
             const float* __restrict__ bv, const float2* __restrict__ cs)
{
    const int z = blockIdx.z;
    const float* bias = (z == 0) ? bq : (z == 1) ? bk : bv;
    hf* oh = (z == 0) ? g_qh : (z == 1) ? g_k : g_v;
    hf* ol = (z == 0) ? g_ql : nullptr;
    mma_gemm_body(xh, xl, g_wh4[z], bias, oh, ol, nullptr, cs, z);
}

__global__ __launch_bounds__(256, 2)
void out_mma(const hf* __restrict__ ah, const hf* __restrict__ al,
             const float* __restrict__ bias, float* __restrict__ out)
{
    mma_gemm_body(ah, al, g_wh4[3], bias, nullptr, nullptr, out, nullptr, 3);
}

// ---------------------------------------------------------------------------
// Register-resident FA2 attention, fp16: Q=Qh+Ql 2-term, K single,
// P single fp16, V single. Triple-buffered cp.async K/V.
// ---------------------------------------------------------------------------
#define ROWB 144
#define KVBUF 18432
#define ATTN_SMEM (3*KVBUF)

__global__ __launch_bounds__(128, 2)
void attn_fa2(const hf* __restrict__ qh, const hf* __restrict__ ql,
              const hf* __restrict__ kk, const hf* __restrict__ vv,
              hf* __restrict__ ah_out, hf* __restrict__ al_out)
{
    extern __shared__ char smem[];
    const uint32_t sbase = smem_u32(smem);

    const int tid  = threadIdx.x;
    const int w    = tid >> 5;
    const int lane = tid & 31;
    const int tig  = lane & 3;
    const int grp  = lane >> 2;
    const int bh = blockIdx.y;
    const int b = bh >> 4, h = bh & (H_-1);
    const int qt = gridDim.x - 1 - blockIdx.x;
    const int q0 = qt << 6;

    const size_t hb = (size_t)bh * T_ * D_;
    const hf* qhb = qh + hb; const hf* qlb = ql + hb;
    const hf* kb_ = kk + hb; const hf* vb_ = vv + hb;

    int jtile[8], jr[8], jv[8];
#pragma unroll
    for (int it = 0; it < 8; it++) {
        const int job = it * 128 + tid;
        jtile[it] = job >> 9;
        jr[it] = (job >> 3) & 63;
        jv[it] = job & 7;
    }
    const hf* ksrc[2] = {kb_, vb_};

#pragma unroll
    for (int it = 0; it < 8; it++)
        CP_ASYNC16(sbase + jtile[it]*9216 + jr[it]*ROWB + jv[it]*16,
                   ksrc[jtile[it]] + (size_t)jr[it]*D_ + jv[it]*8);
    CP_COMMIT();
    if (qt >= 1) {
#pragma unroll
        for (int it = 0; it < 8; it++)
            CP_ASYNC16(sbase + KVBUF + jtile[it]*9216 + jr[it]*ROWB + jv[it]*16,
                       ksrc[jtile[it]] + (size_t)(64*D_) + (size_t)jr[it]*D_ + jv[it]*8);
        CP_COMMIT();
    }

    uint32_t qfh[4][4], qfl[4][4];
    {
        const int r0 = q0 + w*16 + grp;
#pragma unroll
        for (int ks = 0; ks < 4; ks++) {
            const int c = ks*16 + tig*2;
            qfh[ks][0] = *(const uint32_t*)(qhb + (size_t)r0*D_ + c);
            qfh[ks][1] = *(const uint32_t*)(qhb + (size_t)(r0+8)*D_ + c);
            qfh[ks][2] = *(const uint32_t*)(qhb + (size_t)r0*D_ + c + 8);
            qfh[ks][3] = *(const uint32_t*)(qhb + (size_t)(r0+8)*D_ + c + 8);
            qfl[ks][0] = *(const uint32_t*)(qlb + (size_t)r0*D_ + c);
            qfl[ks][1] = *(const uint32_t*)(qlb + (size_t)(r0+8)*D_ + c);
            qfl[ks][2] = *(const uint32_t*)(qlb + (size_t)r0*D_ + c + 8);
            qfl[ks][3] = *(const uint32_t*)(qlb + (size_t)(r0+8)*D_ + c + 8);
        }
    }

    float o[8][4];
#pragma unroll
    for (int t = 0; t < 8; t++)
#pragma unroll
        for (int e = 0; e < 4; e++) o[t][e] = 0.f;

    float m0 = -1e30f, m1 = -1e30f, l0 = 0.f, l1 = 0.f;

    const uint32_t koffA = (uint32_t)((lane & 7) * ROWB + (lane >> 3) * 16);
    const uint32_t voffA = (uint32_t)(((lane >> 3) * 8 + (lane & 7)) * ROWB);

    for (int kt = 0; kt <= qt; kt++) {
        const uint32_t kb = sbase + (kt % 3)*KVBUF;
        const uint32_t vb = kb + 9216;

        if (kt < qt) { CP_WAIT1(); } else { CP_WAIT0(); }
        __syncthreads();

        if (kt + 2 <= qt) {
            const uint32_t db = sbase + ((kt+2) % 3)*KVBUF;
            const size_t soff = (size_t)(kt+2)*64*D_;
#pragma unroll
            for (int it = 0; it < 8; it++)
                CP_ASYNC16(db + jtile[it]*9216 + jr[it]*ROWB + jv[it]*16,
                           ksrc[jtile[it]] + soff + (size_t)jr[it]*D_ + jv[it]*8);
            CP_COMMIT();
        }

        // ---- QK^T (2-term) ----
        float s[8][4];
#pragma unroll
        for (int t = 0; t < 8; t++)
#pragma unroll
            for (int e = 0; e < 4; e++) s[t][e] = 0.f;

#pragma unroll
        for (int t = 0; t < 8; t++) {
#pragma unroll
            for (int kk2 = 0; kk2 < 2; kk2++) {
                uint32_t h0,h1,h2,h3;
                LDSM_X4(h0,h1,h2,h3, kb + (uint32_t)(t*8*ROWB) + (uint32_t)(kk2*64) + koffA);
                const int ks0 = 2*kk2, ks1 = 2*kk2 + 1;
                MMA_F16(s[t], qfh[ks0][0],qfh[ks0][1],qfh[ks0][2],qfh[ks0][3], h0,h1);
                MMA_F16(s[t], qfl[ks0][0],qfl[ks0][1],qfl[ks0][2],qfl[ks0][3], h0,h1);
                MMA_F16(s[t], qfh[ks1][0],qfh[ks1][1],qfh[ks1][2],qfh[ks1][3], h2,h3);
                MMA_F16(s[t], qfl[ks1][0],qfl[ks1][1],qfl[ks1][2],qfl[ks1][3], h2,h3);
            }
        }

        // ---- mask (diag tile only) ----
        if (kt == qt) {
            const int i0 = w*16 + grp, i1 = i0 + 8;
#pragma unroll
            for (int t = 0; t < 8; t++) {
                const int j = t*8 + tig*2;
                if (j   > i0) s[t][0] = -1e30f;
                if (j+1 > i0) s[t][1] = -1e30f;
                if (j   > i1) s[t][2] = -1e30f;
                if (j+1 > i1) s[t][3] = -1e30f;
            }
        }

        // ---- online softmax in registers ----
        float mx0 = -1e30f, mx1 = -1e30f;
#pragma unroll
        for (int t = 0; t < 8; t++) {
            mx0 = fmaxf(mx0, fmaxf(s[t][0], s[t][1]));
            mx1 = fmaxf(mx1, fmaxf(s[t][2], s[t][3]));
        }
        mx0 = fmaxf(mx0, __shfl_xor_sync(0xffffffffu, mx0, 1));
        mx0 = fmaxf(mx0, __shfl_xor_sync(0xffffffffu, mx0, 2));
        mx1 = fmaxf(mx1, __shfl_xor_sync(0xffffffffu, mx1, 1));
        mx1 = fmaxf(mx1, __shfl_xor_sync(0xffffffffu, mx1, 2));

        const float mn0 = fmaxf(m0, mx0), mn1 = fmaxf(m1, mx1);
        const float al0 = exp2p(m0 - mn0), al1 = exp2p(m1 - mn1);
        m0 = mn0; m1 = mn1;

        uint32_t pah0[8], pah1[8];
        float ps0 = 0.f, ps1 = 0.f;
#pragma unroll
        for (int t = 0; t < 8; t++) {
            const float p00 = exp2p(s[t][0] - mn0);
            const float p01 = exp2p(s[t][1] - mn0);
            const float p10 = exp2p(s[t][2] - mn1);
            const float p11 = exp2p(s[t][3] - mn1);
            ps0 += p00 + p01; ps1 += p10 + p11;
            pah0[t] = h2_u32(__floats2half2_rn(p00, p01));
            pah1[t] = h2_u32(__floats2half2_rn(p10, p11));
        }
        ps0 += __shfl_xor_sync(0xffffffffu, ps0, 1);
        ps0 += __shfl_xor_sync(0xffffffffu, ps0, 2);
        ps1 += __shfl_xor_sync(0xffffffffu, ps1, 1);
        ps1 += __shfl_xor_sync(0xffffffffu, ps1, 2);
        l0 = l0 * al0 + ps0;
        l1 = l1 * al1 + ps1;

#pragma unroll
        for (int t = 0; t < 8; t++) {
            o[t][0] *= al0; o[t][1] *= al0;
            o[t][2] *= al1; o[t][3] *= al1;
        }

        // ---- PV (P single fp16) ----
#pragma unroll
        for (int t = 0; t < 8; t++) {
#pragma unroll
            for (int kk2 = 0; kk2 < 2; kk2++) {
                uint32_t h0,h1,h2,h3;
                LDSM_X4T(h0,h1,h2,h3, vb + (uint32_t)(kk2*32*ROWB) + (uint32_t)(t*16) + voffA);
                const int ks0 = 2*kk2, ks1 = 2*kk2 + 1;
                MMA_F16(o[t], pah0[2*ks0],pah1[2*ks0],pah0[2*ks0+1],pah1[2*ks0+1], h0,h1);
                MMA_F16(o[t], pah0[2*ks1],pah1[2*ks1],pah0[2*ks1+1],pah1[2*ks1+1], h2,h3);
            }
        }
    }

    // ---- epilogue: normalize, fp16 split, store [M, C] ----
    const float il0 = 1.f / l0, il1 = 1.f / l1;
    const int r0g = q0 + w*16 + grp;
    const size_t base0 = ((size_t)(b*T_ + r0g)) * C_ + h*D_ + tig*2;
    const size_t base1 = ((size_t)(b*T_ + r0g + 8)) * C_ + h*D_ + tig*2;
#pragma unroll
    for (int t = 0; t < 8; t++) {
        const float v00 = o[t][0]*il0, v01 = o[t][1]*il0;
        const float v10 = o[t][2]*il1, v11 = o[t][3]*il1;
        const __half2 hp0 = __floats2half2_rn(v00, v01);
        const __half2 hp1 = __floats2half2_rn(v10, v11);
        const __half2 lp0 = __floats2half2_rn(v00 - __low2float(hp0), v01 - __high2float(hp0));
        const __half2 lp1 = __floats2half2_rn(v10 - __low2float(hp1), v11 - __high2float(hp1));
        *(__half2*)(ah_out + base0 + t*8) = hp0;
        *(__half2*)(ah_out + base1 + t*8) = hp1;
        *(__half2*)(al_out + base0 + t*8) = lp0;
        *(__half2*)(al_out + base1 + t*8) = lp1;
    }
}

// ---------------------------------------------------------------------------
extern "C" void kernel_launch(void* const* d_in, const int* in_sizes, int n_in,
                              void* d_out, int out_size)
{
    const float* x  = (const float*)d_in[0];
    const float* Wq = (const float*)d_in[1];
    const float* bq = (const float*)d_in[2];
    const float* Wk = (const float*)d_in[3];
    const float* bk = (const float*)d_in[4];
    const float* Wv = (const float*)d_in[5];
    const float* bv = (const float*)d_in[6];
    const float* Wo = (const float*)d_in[7];
    const float* bo = (const float*)d_in[8];
    float* out = (float*)d_out;

    float2* csp;
    hf *xh, *xl, *ah, *al;
    hf *qhp, *qlp, *kp, *vp;
    cudaGetSymbolAddress((void**)&csp,  g_cs);
    cudaGetSymbolAddress((void**)&xh,   g_xh);
    cudaGetSymbolAddress((void**)&xl,   g_xl);
    cudaGetSymbolAddress((void**)&ah,   g_ah);
    cudaGetSymbolAddress((void**)&al,   g_al);
    cudaGetSymbolAddress((void**)&qhp,  g_qh);
    cudaGetSymbolAddress((void**)&qlp,  g_ql);
    cudaGetSymbolAddress((void**)&kp,   g_k);
    cudaGetSymbolAddress((void**)&vp,   g_v);

    rope_table<<<(T_*32)/256, 256>>>(csp);

    cvt_split_h<<<(M_*C_/4)/256, 256>>>(x, xh, xl, M_*C_/4);
    cvt_w_h<<<dim3((C_*C_/4)/256, 1, 4), 256>>>(Wq, Wk, Wv, Wo);

    const size_t gsmem = 2*STAGE_HB + 512;  // 111104 B
    cudaFuncSetAttribute(qkv_mma, cudaFuncAttributeMaxDynamicSharedMemorySize, (int)gsmem);
    cudaFuncSetAttribute(out_mma, cudaFuncAttributeMaxDynamicSharedMemorySize, (int)gsmem);
    cudaFuncSetAttribute(attn_fa2, cudaFuncAttributeMaxDynamicSharedMemorySize, ATTN_SMEM);

    qkv_mma<<<dim3(C_/128, M_/128, 3), 256, gsmem>>>(xh, xl, bq, bk, bv, csp);

    attn_fa2<<<dim3(T_/64, B_*H_), 128, ATTN_SMEM>>>(qhp, qlp, kp, vp, ah, al);

    out_mma<<<dim3(C_/128, M_/128), 256, gsmem>>>(ah, al, bo, out);
}

// round 17
// speedup vs baseline: 1.8630x; 1.1642x over previous
#include <cuda_runtime.h>
#include <cuda_bf16.h>
#include <cuda_fp16.h>
#include <mma.h>
#include <math.h>
#include <stdint.h>

using namespace nvcuda;

#define B_ 2
#define T_ 2048
#define C_ 1024
#define H_ 16
#define D_ 64
#define M_ (B_*T_)
#define QSCALE 0.1803368801111437f  // (1/sqrt(64)) * log2(e)

typedef __half hf;

// ---------------------------------------------------------------------------
// Scratch (allocation-free contract: __device__ globals)
// ---------------------------------------------------------------------------
__device__ float2 g_cs[T_*32];
__device__ hf g_xh[M_*C_], g_xl[M_*C_];          // x split (fp16 2-term)
__device__ hf g_a[M_*C_];                         // attention out (single fp16)
__device__ hf g_wh4[4][C_*C_];                    // weights single fp16
__device__ hf g_q[B_*H_*T_*D_];                   // q single fp16 (qscale folded)
__device__ hf g_k[B_*H_*T_*D_];                   // k single fp16
__device__ hf g_v[B_*H_*T_*D_];                   // v single fp16

// ---------------------------------------------------------------------------
// cp.async / ldmatrix / mma helpers
// ---------------------------------------------------------------------------
#define CP_ASYNC16(dst, src) \
    asm volatile("cp.async.cg.shared.global [%0], [%1], 16;" :: "r"(dst), "l"(src) : "memory")
#define CP_COMMIT() asm volatile("cp.async.commit_group;" ::: "memory")
#define CP_WAIT0()  asm volatile("cp.async.wait_group 0;" ::: "memory")
#define CP_WAIT1()  asm volatile("cp.async.wait_group 1;" ::: "memory")

#define LDSM_X4(r0,r1,r2,r3, a) \
    asm volatile("ldmatrix.sync.aligned.m8n8.x4.shared.b16 {%0,%1,%2,%3}, [%4];" \
        : "=r"(r0),"=r"(r1),"=r"(r2),"=r"(r3) : "r"(a))
#define LDSM_X4T(r0,r1,r2,r3, a) \
    asm volatile("ldmatrix.sync.aligned.m8n8.x4.trans.shared.b16 {%0,%1,%2,%3}, [%4];" \
        : "=r"(r0),"=r"(r1),"=r"(r2),"=r"(r3) : "r"(a))

#define MMA_F16(d, a0,a1,a2,a3, b0,b1) \
    asm volatile("mma.sync.aligned.m16n8k16.row.col.f32.f16.f16.f32 " \
        "{%0,%1,%2,%3},{%4,%5,%6,%7},{%8,%9},{%0,%1,%2,%3};" \
        : "+f"((d)[0]),"+f"((d)[1]),"+f"((d)[2]),"+f"((d)[3]) \
        : "r"(a0),"r"(a1),"r"(a2),"r"(a3), "r"(b0),"r"(b1))

__device__ __forceinline__ uint32_t smem_u32(const void* p) {
    uint32_t a;
    asm("{ .reg .u64 t; cvta.to.shared.u64 t, %1; cvt.u32.u64 %0, t; }" : "=r"(a) : "l"(p));
    return a;
}

__device__ __forceinline__ uint32_t h2_u32(__half2 v) {
    return *reinterpret_cast<uint32_t*>(&v);
}

// ---------------------------------------------------------------------------
// FMA-pipe exp2: x <= 0
// ---------------------------------------------------------------------------
__device__ __forceinline__ float exp2p(float x)
{
    x = fmaxf(x, -125.0f);
    const float r = rintf(x);
    const float f = x - r;
    float p = 0.0013333558f;
    p = fmaf(p, f, 0.0096181291f);
    p = fmaf(p, f, 0.0555041087f);
    p = fmaf(p, f, 0.2402265070f);
    p = fmaf(p, f, 0.6931471806f);
    p = fmaf(p, f, 1.0f);
    const int e = (int)r;
    return p * __int_as_float((e + 127) << 23);
}

// ---------------------------------------------------------------------------
// RoPE table
// ---------------------------------------------------------------------------
__global__ void rope_table(float2* __restrict__ tab)
{
    const int idx = blockIdx.x * blockDim.x + threadIdx.x;
    if (idx >= T_*32) return;
    const int t = idx >> 5, i = idx & 31;
    const double inv = pow(10000.0, -(double)(2*i) / 64.0);
    const double ang = (double)t * inv;
    tab[idx] = make_float2((float)cos(ang), (float)sin(ang));
}

// ---------------------------------------------------------------------------
// fp32 -> (fp16 hi, fp16 lo) split for activations
// ---------------------------------------------------------------------------
__global__ __launch_bounds__(256)
void cvt_split_h(const float* __restrict__ in, hf* __restrict__ hi,
                 hf* __restrict__ lo, int n4)
{
    const int i = blockIdx.x * blockDim.x + threadIdx.x;
    if (i >= n4) return;
    const float4 v = ((const float4*)in)[i];
    const float f[4] = {v.x, v.y, v.z, v.w};
    hf h[4], l[4];
#pragma unroll
    for (int j = 0; j < 4; j++) {
        h[j] = __float2half_rn(f[j]);
        l[j] = __float2half_rn(f[j] - __half2float(h[j]));
    }
    ((__half2*)hi)[2*i]   = __half2(h[0], h[1]);
    ((__half2*)hi)[2*i+1] = __half2(h[2], h[3]);
    ((__half2*)lo)[2*i]   = __half2(l[0], l[1]);
    ((__half2*)lo)[2*i+1] = __half2(l[2], l[3]);
}

// all 4 weights -> single fp16, one launch
__global__ __launch_bounds__(256)
void cvt_w_h(const float* __restrict__ w0, const float* __restrict__ w1,
             const float* __restrict__ w2, const float* __restrict__ w3)
{
    const int i = blockIdx.x * blockDim.x + threadIdx.x;
    if (i >= C_*C_/4) return;
    const int z = blockIdx.z;
    const float* in = (z == 0) ? w0 : (z == 1) ? w1 : (z == 2) ? w2 : w3;
    const float4 v = ((const float4*)in)[i];
    hf* dst = g_wh4[z];
    ((__half2*)dst)[2*i]   = __floats2half2_rn(v.x, v.y);
    ((__half2*)dst)[2*i+1] = __floats2half2_rn(v.z, v.w);
}

// ---------------------------------------------------------------------------
// Pipelined wmma fp16 GEMM, KC=64 chunks, cp.async double buffer.
// TWO=1: D = Ah*Wh + Al*Wh (x projections). TWO=0: D = Ah*Wh (out proj).
// z=0: q (rope+qscale -> fp16), z=1: k (rope -> fp16), z=2: v (fp16),
// z=3: fp32 out.
// ---------------------------------------------------------------------------
#define SLDB 72                        // fp16 leading dim (144B rows)
#define TILE_HB (128*SLDB*2)           // 18432 B per tile
#define LDE 132
#define NCH (C_/64)                    // 16 chunks
#define GSMEM (2*3*TILE_HB + 512)      // worst case (TWO=1)

template <int TWO>
__device__ __forceinline__
void mma_gemm_body(const hf* __restrict__ Ah, const hf* __restrict__ Al,
                   const hf* __restrict__ Wh,
                   const float* __restrict__ bias,
                   hf* __restrict__ oh, float* __restrict__ of,
                   const float2* __restrict__ cs, int z)
{
    constexpr int NT = TWO ? 3 : 2;                // tiles per stage
    constexpr int STAGE = NT * TILE_HB;
    constexpr int NJOB = TWO ? 12 : 8;             // 16B vecs per thread
    extern __shared__ char smem[];
    const uint32_t sbase = smem_u32(smem);
    float* sEpi   = (float*)smem;
    float* bias_s = (float*)(smem + 2*STAGE);

    const int tid = threadIdx.x;
    const int wid = tid >> 5;
    const int wm = wid >> 2;
    const int wn = wid & 3;
    const int m0 = blockIdx.y << 7, n0 = blockIdx.x << 7;

    if (tid < 128) bias_s[tid] = bias[n0 + tid];

    const hf* srcs[NT];
    int row0[NT];
    srcs[0] = Ah; row0[0] = m0;
    if (TWO) { srcs[1] = Al; row0[1] = m0; srcs[NT-1] = Wh; row0[NT-1] = n0; }
    else     { srcs[1] = Wh; row0[1] = n0; }

    int jtile[NJOB], jr[NJOB], jv[NJOB];
#pragma unroll
    for (int it = 0; it < NJOB; it++) {
        const int job = it * 256 + tid;
        jtile[it] = job >> 10;
        const int idx = job & 1023;
        jr[it] = idx >> 3;
        jv[it] = idx & 7;
    }

#pragma unroll
    for (int it = 0; it < NJOB; it++) {
        const hf* g = srcs[jtile[it]] + (size_t)(row0[jtile[it]] + jr[it]) * C_ + jv[it]*8;
        CP_ASYNC16(sbase + jtile[it]*TILE_HB + jr[it]*144 + jv[it]*16, g);
    }
    CP_COMMIT();

    wmma::fragment<wmma::accumulator, 16, 16, 16, float> acc[4][2];
#pragma unroll
    for (int mt = 0; mt < 4; mt++)
#pragma unroll
        for (int nt = 0; nt < 2; nt++) wmma::fill_fragment(acc[mt][nt], 0.f);

    for (int kc = 0; kc < NCH; kc++) {
        const int s = kc & 1;
        if (kc + 1 < NCH) {
            const uint32_t db = sbase + (s^1)*STAGE;
            const int koff = (kc+1)*64;
#pragma unroll
            for (int it = 0; it < NJOB; it++) {
                const hf* g = srcs[jtile[it]] + (size_t)(row0[jtile[it]] + jr[it]) * C_ + koff + jv[it]*8;
                CP_ASYNC16(db + jtile[it]*TILE_HB + jr[it]*144 + jv[it]*16, g);
            }
            CP_COMMIT();
            CP_WAIT1();
        } else {
            CP_WAIT0();
        }
        __syncthreads();

        hf* sT = (hf*)(smem + s*STAGE);
#pragma unroll
        for (int ks = 0; ks < 4; ks++) {
            wmma::fragment<wmma::matrix_b, 16, 16, 16, hf, wmma::col_major> fwh[2];
#pragma unroll
            for (int nt = 0; nt < 2; nt++)
                wmma::load_matrix_sync(fwh[nt], sT + (NT-1)*(128*SLDB) + (wn*32 + nt*16)*SLDB + ks*16, SLDB);
#pragma unroll
            for (int mt = 0; mt < 4; mt++) {
                wmma::fragment<wmma::matrix_a, 16, 16, 16, hf, wmma::row_major> fah;
                wmma::load_matrix_sync(fah, sT + 0*(128*SLDB) + (wm*64 + mt*16)*SLDB + ks*16, SLDB);
#pragma unroll
                for (int nt = 0; nt < 2; nt++)
                    wmma::mma_sync(acc[mt][nt], fah, fwh[nt], acc[mt][nt]);
                if (TWO) {
                    wmma::fragment<wmma::matrix_a, 16, 16, 16, hf, wmma::row_major> fal;
                    wmma::load_matrix_sync(fal, sT + 1*(128*SLDB) + (wm*64 + mt*16)*SLDB + ks*16, SLDB);
#pragma unroll
                    for (int nt = 0; nt < 2; nt++)
                        wmma::mma_sync(acc[mt][nt], fal, fwh[nt], acc[mt][nt]);
                }
            }
        }
        __syncthreads();
    }

#pragma unroll
    for (int mt = 0; mt < 4; mt++)
#pragma unroll
        for (int nt = 0; nt < 2; nt++)
            wmma::store_matrix_sync(sEpi + (wm*64 + mt*16)*LDE + wn*32 + nt*16,
                                    acc[mt][nt], LDE, wmma::mem_row_major);
    __syncthreads();

    const int tx = tid & 15, ty = tid >> 4;
    const int n_base = n0 + 8*tx;
    const float4 b0 = *(const float4*)&bias_s[8*tx];
    const float4 b1 = *(const float4*)&bias_s[8*tx + 4];
    const float bb[8] = {b0.x, b0.y, b0.z, b0.w, b1.x, b1.y, b1.z, b1.w};

#pragma unroll
    for (int r = 0; r < 8; r++) {
        const int lrow = 8*ty + r;
        const int m = m0 + lrow;
        float o[8];
#pragma unroll
        for (int j = 0; j < 8; j++) o[j] = sEpi[lrow*LDE + 8*tx + j] + bb[j];

        if (z < 2) {  // RoPE
            const int t = m & (T_-1);
#pragma unroll
            for (int p = 0; p < 4; p++) {
                const int i = ((n_base + 2*p) & 63) >> 1;
                const float2 csv = cs[t*32 + i];
                const float x1 = o[2*p], x2 = o[2*p+1];
                o[2*p]   = x1*csv.x - x2*csv.y;
                o[2*p+1] = x1*csv.y + x2*csv.x;
            }
        }
        if (z == 0) {
#pragma unroll
            for (int j = 0; j < 8; j++) o[j] *= QSCALE;
        }

        if (z <= 2) {
            const int b = m >> 11, t = m & (T_-1);
            const int h = n_base >> 6, d = n_base & 63;
            const size_t doff = (((size_t)(b*H_ + h) * T_) + t) * D_ + d;
            hf h8[8];
#pragma unroll
            for (int j = 0; j < 8; j++) h8[j] = __float2half_rn(o[j]);
            *(uint4*)(oh + doff) = *(uint4*)h8;
        } else {
            float* dst = of + (size_t)m * C_ + n_base;
            *(float4*)dst = make_float4(o[0], o[1], o[2], o[3]);
            *(float4*)(dst + 4) = make_float4(o[4], o[5], o[6], o[7]);
        }
    }
}

__global__ __launch_bounds__(256, 2)
void qkv_mma(const hf* __restrict__ xh, const hf* __restrict__ xl,
             const float* __restrict__ bq, const float* __restrict__ bk,
             const float* __restrict__ bv, const float2* __restrict__ cs)
{
    const int z = blockIdx.z;
    const float* bias = (z == 0) ? bq : (z == 1) ? bk : bv;
    hf* oh = (z == 0) ? g_q : (z == 1) ? g_k : g_v;
    mma_gemm_body<1>(xh, xl, g_wh4[z], bias, oh, nullptr, cs, z);
}

__global__ __launch_bounds__(256, 2)
void out_mma(const hf* __restrict__ a, const float* __restrict__ bias,
             float* __restrict__ out)
{
    mma_gemm_body<0>(a, nullptr, g_wh4[3], bias, nullptr, out, nullptr, 3);
}

// ---------------------------------------------------------------------------
// Register-resident FA2 attention, all-single fp16 operands (Q, K, P, V).
// Triple-buffered cp.async K/V.
// ---------------------------------------------------------------------------
#define ROWB 144
#define KVBUF 18432
#define ATTN_SMEM (3*KVBUF)

__global__ __launch_bounds__(128, 3)
void attn_fa2(const hf* __restrict__ qq, const hf* __restrict__ kk,
              const hf* __restrict__ vv, hf* __restrict__ a_out)
{
    extern __shared__ char smem[];
    const uint32_t sbase = smem_u32(smem);

    const int tid  = threadIdx.x;
    const int w    = tid >> 5;
    const int lane = tid & 31;
    const int tig  = lane & 3;
    const int grp  = lane >> 2;
    const int bh = blockIdx.y;
    const int b = bh >> 4, h = bh & (H_-1);
    const int qt = gridDim.x - 1 - blockIdx.x;
    const int q0 = qt << 6;

    const size_t hb = (size_t)bh * T_ * D_;
    const hf* qb_ = qq + hb;
    const hf* kb_ = kk + hb;
    const hf* vb_ = vv + hb;

    int jtile[8], jr[8], jv[8];
#pragma unroll
    for (int it = 0; it < 8; it++) {
        const int job = it * 128 + tid;
        jtile[it] = job >> 9;
        jr[it] = (job >> 3) & 63;
        jv[it] = job & 7;
    }
    const hf* ksrc[2] = {kb_, vb_};

#pragma unroll
    for (int it = 0; it < 8; it++)
        CP_ASYNC16(sbase + jtile[it]*9216 + jr[it]*ROWB + jv[it]*16,
                   ksrc[jtile[it]] + (size_t)jr[it]*D_ + jv[it]*8);
    CP_COMMIT();
    if (qt >= 1) {
#pragma unroll
        for (int it = 0; it < 8; it++)
            CP_ASYNC16(sbase + KVBUF + jtile[it]*9216 + jr[it]*ROWB + jv[it]*16,
                       ksrc[jtile[it]] + (size_t)(64*D_) + (size_t)jr[it]*D_ + jv[it]*8);
        CP_COMMIT();
    }

    // Q fragments (single fp16) from gmem, kept for whole kernel
    uint32_t qf[4][4];
    {
        const int r0 = q0 + w*16 + grp;
#pragma unroll
        for (int ks = 0; ks < 4; ks++) {
            const int c = ks*16 + tig*2;
            qf[ks][0] = *(const uint32_t*)(qb_ + (size_t)r0*D_ + c);
            qf[ks][1] = *(const uint32_t*)(qb_ + (size_t)(r0+8)*D_ + c);
            qf[ks][2] = *(const uint32_t*)(qb_ + (size_t)r0*D_ + c + 8);
            qf[ks][3] = *(const uint32_t*)(qb_ + (size_t)(r0+8)*D_ + c + 8);
        }
    }

    float o[8][4];
#pragma unroll
    for (int t = 0; t < 8; t++)
#pragma unroll
        for (int e = 0; e < 4; e++) o[t][e] = 0.f;

    float m0 = -1e30f, m1 = -1e30f, l0 = 0.f, l1 = 0.f;

    const uint32_t koffA = (uint32_t)((lane & 7) * ROWB + (lane >> 3) * 16);
    const uint32_t voffA = (uint32_t)(((lane >> 3) * 8 + (lane & 7)) * ROWB);

    for (int kt = 0; kt <= qt; kt++) {
        const uint32_t kb = sbase + (kt % 3)*KVBUF;
        const uint32_t vb = kb + 9216;

        if (kt < qt) { CP_WAIT1(); } else { CP_WAIT0(); }
        __syncthreads();

        if (kt + 2 <= qt) {
            const uint32_t db = sbase + ((kt+2) % 3)*KVBUF;
            const size_t soff = (size_t)(kt+2)*64*D_;
#pragma unroll
            for (int it = 0; it < 8; it++)
                CP_ASYNC16(db + jtile[it]*9216 + jr[it]*ROWB + jv[it]*16,
                           ksrc[jtile[it]] + soff + (size_t)jr[it]*D_ + jv[it]*8);
            CP_COMMIT();
        }

        // ---- QK^T (single-term) ----
        float s[8][4];
#pragma unroll
        for (int t = 0; t < 8; t++)
#pragma unroll
            for (int e = 0; e < 4; e++) s[t][e] = 0.f;

#pragma unroll
        for (int t = 0; t < 8; t++) {
#pragma unroll
            for (int kk2 = 0; kk2 < 2; kk2++) {
                uint32_t h0,h1,h2,h3;
                LDSM_X4(h0,h1,h2,h3, kb + (uint32_t)(t*8*ROWB) + (uint32_t)(kk2*64) + koffA);
                const int ks0 = 2*kk2, ks1 = 2*kk2 + 1;
                MMA_F16(s[t], qf[ks0][0],qf[ks0][1],qf[ks0][2],qf[ks0][3], h0,h1);
                MMA_F16(s[t], qf[ks1][0],qf[ks1][1],qf[ks1][2],qf[ks1][3], h2,h3);
            }
        }

        // ---- mask (diag tile only) ----
        if (kt == qt) {
            const int i0 = w*16 + grp, i1 = i0 + 8;
#pragma unroll
            for (int t = 0; t < 8; t++) {
                const int j = t*8 + tig*2;
                if (j   > i0) s[t][0] = -1e30f;
                if (j+1 > i0) s[t][1] = -1e30f;
                if (j   > i1) s[t][2] = -1e30f;
                if (j+1 > i1) s[t][3] = -1e30f;
            }
        }

        // ---- online softmax in registers ----
        float mx0 = -1e30f, mx1 = -1e30f;
#pragma unroll
        for (int t = 0; t < 8; t++) {
            mx0 = fmaxf(mx0, fmaxf(s[t][0], s[t][1]));
            mx1 = fmaxf(mx1, fmaxf(s[t][2], s[t][3]));
        }
        mx0 = fmaxf(mx0, __shfl_xor_sync(0xffffffffu, mx0, 1));
        mx0 = fmaxf(mx0, __shfl_xor_sync(0xffffffffu, mx0, 2));
        mx1 = fmaxf(mx1, __shfl_xor_sync(0xffffffffu, mx1, 1));
        mx1 = fmaxf(mx1, __shfl_xor_sync(0xffffffffu, mx1, 2));

        const float mn0 = fmaxf(m0, mx0), mn1 = fmaxf(m1, mx1);
        const float al0 = exp2p(m0 - mn0), al1 = exp2p(m1 - mn1);
        m0 = mn0; m1 = mn1;

        uint32_t pah0[8], pah1[8];
        float ps0 = 0.f, ps1 = 0.f;
#pragma unroll
        for (int t = 0; t < 8; t++) {
            const float p00 = exp2p(s[t][0] - mn0);
            const float p01 = exp2p(s[t][1] - mn0);
            const float p10 = exp2p(s[t][2] - mn1);
            const float p11 = exp2p(s[t][3] - mn1);
            ps0 += p00 + p01; ps1 += p10 + p11;
            pah0[t] = h2_u32(__floats2half2_rn(p00, p01));
            pah1[t] = h2_u32(__floats2half2_rn(p10, p11));
        }
        ps0 += __shfl_xor_sync(0xffffffffu, ps0, 1);
        ps0 += __shfl_xor_sync(0xffffffffu, ps0, 2);
        ps1 += __shfl_xor_sync(0xffffffffu, ps1, 1);
        ps1 += __shfl_xor_sync(0xffffffffu, ps1, 2);
        l0 = l0 * al0 + ps0;
        l1 = l1 * al1 + ps1;

#pragma unroll
        for (int t = 0; t < 8; t++) {
            o[t][0] *= al0; o[t][1] *= al0;
            o[t][2] *= al1; o[t][3] *= al1;
        }

        // ---- PV (single-term) ----
#pragma unroll
        for (int t = 0; t < 8; t++) {
#pragma unroll
            for (int kk2 = 0; kk2 < 2; kk2++) {
                uint32_t h0,h1,h2,h3;
                LDSM_X4T(h0,h1,h2,h3, vb + (uint32_t)(kk2*32*ROWB) + (uint32_t)(t*16) + voffA);
                const int ks0 = 2*kk2, ks1 = 2*kk2 + 1;
                MMA_F16(o[t], pah0[2*ks0],pah1[2*ks0],pah0[2*ks0+1],pah1[2*ks0+1], h0,h1);
                MMA_F16(o[t], pah0[2*ks1],pah1[2*ks1],pah0[2*ks1+1],pah1[2*ks1+1], h2,h3);
            }
        }
    }

    // ---- epilogue: normalize, single fp16 store [M, C] ----
    const float il0 = 1.f / l0, il1 = 1.f / l1;
    const int r0g = q0 + w*16 + grp;
    const size_t base0 = ((size_t)(b*T_ + r0g)) * C_ + h*D_ + tig*2;
    const size_t base1 = ((size_t)(b*T_ + r0g + 8)) * C_ + h*D_ + tig*2;
#pragma unroll
    for (int t = 0; t < 8; t++) {
        const __half2 hp0 = __floats2half2_rn(o[t][0]*il0, o[t][1]*il0);
        const __half2 hp1 = __floats2half2_rn(o[t][2]*il1, o[t][3]*il1);
        *(__half2*)(a_out + base0 + t*8) = hp0;
        *(__half2*)(a_out + base1 + t*8) = hp1;
    }
}

// ---------------------------------------------------------------------------
extern "C" void kernel_launch(void* const* d_in, const int* in_sizes, int n_in,
                              void* d_out, int out_size)
{
    const float* x  = (const float*)d_in[0];
    const float* Wq = (const float*)d_in[1];
    const float* bq = (const float*)d_in[2];
    const float* Wk = (const float*)d_in[3];
    const float* bk = (const float*)d_in[4];
    const float* Wv = (const float*)d_in[5];
    const float* bv = (const float*)d_in[6];
    const float* Wo = (const float*)d_in[7];
    const float* bo = (const float*)d_in[8];
    float* out = (float*)d_out;

    float2* csp;
    hf *xh, *xl, *ap;
    hf *qp, *kp, *vp;
    cudaGetSymbolAddress((void**)&csp, g_cs);
    cudaGetSymbolAddress((void**)&xh,  g_xh);
    cudaGetSymbolAddress((void**)&xl,  g_xl);
    cudaGetSymbolAddress((void**)&ap,  g_a);
    cudaGetSymbolAddress((void**)&qp,  g_q);
    cudaGetSymbolAddress((void**)&kp,  g_k);
    cudaGetSymbolAddress((void**)&vp,  g_v);

    rope_table<<<(T_*32)/256, 256>>>(csp);

    cvt_split_h<<<(M_*C_/4)/256, 256>>>(x, xh, xl, M_*C_/4);
    cvt_w_h<<<dim3((C_*C_/4)/256, 1, 4), 256>>>(Wq, Wk, Wv, Wo);

    cudaFuncSetAttribute(qkv_mma, cudaFuncAttributeMaxDynamicSharedMemorySize, GSMEM);
    cudaFuncSetAttribute(out_mma, cudaFuncAttributeMaxDynamicSharedMemorySize, GSMEM);
    cudaFuncSetAttribute(attn_fa2, cudaFuncAttributeMaxDynamicSharedMemorySize, ATTN_SMEM);

    qkv_mma<<<dim3(C_/128, M_/128, 3), 256, GSMEM>>>(xh, xl, bq, bk, bv, csp);

    attn_fa2<<<dim3(T_/64, B_*H_), 128, ATTN_SMEM>>>(qp, kp, vp, ap);

    out_mma<<<dim3(C_/128, M_/128), 256, GSMEM>>>(ap, bo, out);
}